// round 1
// baseline (speedup 1.0000x reference)
#include <cuda_runtime.h>

#define SEQ   2048
#define DM    2048
#define NQ    32
#define NKV   8
#define HD    64
#define NREP  (NQ / NKV)
#define QKVN  3072           // HD*(NQ+2*NKV)
#define BATCH 2
#define MTOT  (BATCH * SEQ)  // 4096

// ---------------- scratch (device globals: allocation-free) ----------------
__device__ float g_qkv[(size_t)MTOT * QKVN];                 // 50 MB
__device__ float g_scores[(size_t)BATCH * NQ * SEQ * SEQ];   // 1.07 GB
__device__ float g_attn[(size_t)MTOT * DM];                  // 33 MB

// ---------------- generic NN SGEMM + bias: C[M,N] = A[M,K]B[K,N] + bias ----
template <int BM, int BN, int BK, int TM, int TN>
__global__ __launch_bounds__(256)
void sgemm_bias(const float* __restrict__ A, const float* __restrict__ B,
                const float* __restrict__ bias, float* __restrict__ C,
                int M, int N, int K) {
    constexpr int THREADS = (BM / TM) * (BN / TN);  // 256
    __shared__ float As[BK][BM];
    __shared__ float Bs[BK][BN];
    const int tid = threadIdx.x;
    const int tx = tid % (BN / TN);
    const int ty = tid / (BN / TN);
    const int m0 = blockIdx.y * BM;
    const int n0 = blockIdx.x * BN;

    float acc[TM][TN] = {};

    for (int kt = 0; kt < K; kt += BK) {
        // A tile: BM x BK, store transposed
        #pragma unroll
        for (int i = 0; i < (BM * BK) / (4 * THREADS); i++) {
            int idx = tid + i * THREADS;
            int row = idx / (BK / 4);
            int c4  = idx % (BK / 4);
            float4 v = *(const float4*)(A + (size_t)(m0 + row) * K + kt + c4 * 4);
            As[c4 * 4 + 0][row] = v.x;
            As[c4 * 4 + 1][row] = v.y;
            As[c4 * 4 + 2][row] = v.z;
            As[c4 * 4 + 3][row] = v.w;
        }
        // B tile: BK x BN
        #pragma unroll
        for (int i = 0; i < (BK * BN) / (4 * THREADS); i++) {
            int idx = tid + i * THREADS;
            int row = idx / (BN / 4);
            int c4  = idx % (BN / 4);
            *(float4*)&Bs[row][c4 * 4] =
                *(const float4*)(B + (size_t)(kt + row) * N + n0 + c4 * 4);
        }
        __syncthreads();
        #pragma unroll
        for (int kk = 0; kk < BK; kk++) {
            float a[TM], b[TN];
            #pragma unroll
            for (int i = 0; i < TM; i += 4)
                *(float4*)&a[i] = *(float4*)&As[kk][ty * TM + i];
            #pragma unroll
            for (int j = 0; j < TN; j += 4)
                *(float4*)&b[j] = *(float4*)&Bs[kk][tx * TN + j];
            #pragma unroll
            for (int i = 0; i < TM; i++)
                #pragma unroll
                for (int j = 0; j < TN; j++)
                    acc[i][j] += a[i] * b[j];
        }
        __syncthreads();
    }

    #pragma unroll
    for (int i = 0; i < TM; i++) {
        int m = m0 + ty * TM + i;
        #pragma unroll
        for (int j = 0; j < TN; j += 4) {
            int n = n0 + tx * TN + j;
            float4 v;
            v.x = acc[i][j + 0] + bias[n + 0];
            v.y = acc[i][j + 1] + bias[n + 1];
            v.z = acc[i][j + 2] + bias[n + 2];
            v.w = acc[i][j + 3] + bias[n + 3];
            *(float4*)(C + (size_t)m * N + n) = v;
        }
    }
}

// ---------------- scores: S[z] = (Q_z K_z^T) / 8, batched over z=(b,h) -----
__global__ __launch_bounds__(256)
void score_kernel(const float* __restrict__ qkv, float* __restrict__ scores) {
    constexpr int BM = 128, BN = 128, BK = 16, TM = 8, TN = 8, THREADS = 256;
    __shared__ float As[BK][BM];
    __shared__ float Bs[BK][BN];
    const int z = blockIdx.z;
    const int b = z / NQ;
    const int h = z % NQ;
    const float* Qb = qkv + (size_t)b * SEQ * QKVN + h * HD;
    const float* Kb = qkv + (size_t)b * SEQ * QKVN + NQ * HD + (h / NREP) * HD;
    float* Sb = scores + (size_t)z * SEQ * SEQ;

    const int tid = threadIdx.x;
    const int tx = tid % (BN / TN);
    const int ty = tid / (BN / TN);
    const int m0 = blockIdx.y * BM;
    const int n0 = blockIdx.x * BN;

    float acc[TM][TN] = {};

    for (int kt = 0; kt < HD; kt += BK) {
        #pragma unroll
        for (int i = 0; i < 2; i++) {
            int idx = tid + i * THREADS;
            int row = idx / 4, c4 = idx % 4;
            float4 v = *(const float4*)(Qb + (size_t)(m0 + row) * QKVN + kt + c4 * 4);
            As[c4 * 4 + 0][row] = v.x;
            As[c4 * 4 + 1][row] = v.y;
            As[c4 * 4 + 2][row] = v.z;
            As[c4 * 4 + 3][row] = v.w;
        }
        #pragma unroll
        for (int i = 0; i < 2; i++) {
            int idx = tid + i * THREADS;
            int row = idx / 4, c4 = idx % 4;
            float4 v = *(const float4*)(Kb + (size_t)(n0 + row) * QKVN + kt + c4 * 4);
            Bs[c4 * 4 + 0][row] = v.x;
            Bs[c4 * 4 + 1][row] = v.y;
            Bs[c4 * 4 + 2][row] = v.z;
            Bs[c4 * 4 + 3][row] = v.w;
        }
        __syncthreads();
        #pragma unroll
        for (int kk = 0; kk < BK; kk++) {
            float a[TM], bfr[TN];
            #pragma unroll
            for (int i = 0; i < TM; i += 4)
                *(float4*)&a[i] = *(float4*)&As[kk][ty * TM + i];
            #pragma unroll
            for (int j = 0; j < TN; j += 4)
                *(float4*)&bfr[j] = *(float4*)&Bs[kk][tx * TN + j];
            #pragma unroll
            for (int i = 0; i < TM; i++)
                #pragma unroll
                for (int j = 0; j < TN; j++)
                    acc[i][j] += a[i] * bfr[j];
        }
        __syncthreads();
    }

    const float scale = 0.125f;  // 1/sqrt(64)
    #pragma unroll
    for (int i = 0; i < TM; i++) {
        int m = m0 + ty * TM + i;
        #pragma unroll
        for (int j = 0; j < TN; j += 4) {
            int n = n0 + tx * TN + j;
            float4 v;
            v.x = acc[i][j + 0] * scale;
            v.y = acc[i][j + 1] * scale;
            v.z = acc[i][j + 2] * scale;
            v.w = acc[i][j + 3] * scale;
            *(float4*)(Sb + (size_t)m * SEQ + n) = v;
        }
    }
}

// ---------------- softmax over rows of length SEQ --------------------------
__global__ __launch_bounds__(256)
void softmax_kernel(float* __restrict__ scores) {
    const size_t row = (size_t)blockIdx.x + (size_t)blockIdx.y * gridDim.x;
    float4* p = (float4*)(scores + row * SEQ);
    const int tid = threadIdx.x;
    __shared__ float red_m[8];
    __shared__ float red_s[8];

    float4 v0 = p[tid];
    float4 v1 = p[tid + 256];

    float m = fmaxf(fmaxf(fmaxf(v0.x, v0.y), fmaxf(v0.z, v0.w)),
                    fmaxf(fmaxf(v1.x, v1.y), fmaxf(v1.z, v1.w)));
    #pragma unroll
    for (int o = 16; o; o >>= 1) m = fmaxf(m, __shfl_xor_sync(0xffffffffu, m, o));
    if ((tid & 31) == 0) red_m[tid >> 5] = m;
    __syncthreads();
    m = fmaxf(fmaxf(fmaxf(red_m[0], red_m[1]), fmaxf(red_m[2], red_m[3])),
              fmaxf(fmaxf(red_m[4], red_m[5]), fmaxf(red_m[6], red_m[7])));

    v0.x = __expf(v0.x - m); v0.y = __expf(v0.y - m);
    v0.z = __expf(v0.z - m); v0.w = __expf(v0.w - m);
    v1.x = __expf(v1.x - m); v1.y = __expf(v1.y - m);
    v1.z = __expf(v1.z - m); v1.w = __expf(v1.w - m);

    float s = (v0.x + v0.y) + (v0.z + v0.w) + (v1.x + v1.y) + (v1.z + v1.w);
    #pragma unroll
    for (int o = 16; o; o >>= 1) s += __shfl_xor_sync(0xffffffffu, s, o);
    if ((tid & 31) == 0) red_s[tid >> 5] = s;
    __syncthreads();
    s = (red_s[0] + red_s[1]) + (red_s[2] + red_s[3]) +
        (red_s[4] + red_s[5]) + (red_s[6] + red_s[7]);

    const float inv = 1.0f / s;
    v0.x *= inv; v0.y *= inv; v0.z *= inv; v0.w *= inv;
    v1.x *= inv; v1.y *= inv; v1.z *= inv; v1.w *= inv;
    p[tid] = v0;
    p[tid + 256] = v1;
}

// ---------------- PV: O[z] = P[z] @ V_z, batched over z --------------------
__global__ __launch_bounds__(256)
void pv_kernel(const float* __restrict__ scores, const float* __restrict__ qkv,
               float* __restrict__ attn) {
    constexpr int BM = 128, BN = 64, BK = 16, TM = 8, TN = 4, THREADS = 256;
    __shared__ float As[BK][BM];
    __shared__ float Bs[BK][BN];
    const int z = blockIdx.z;
    const int b = z / NQ;
    const int h = z % NQ;
    const float* P = scores + (size_t)z * SEQ * SEQ;
    const float* V = qkv + (size_t)b * SEQ * QKVN + (NQ + NKV) * HD + (h / NREP) * HD;
    float* C = attn + (size_t)b * SEQ * DM + h * HD;

    const int tid = threadIdx.x;
    const int tx = tid % (BN / TN);   // 16
    const int ty = tid / (BN / TN);   // 16
    const int m0 = blockIdx.y * BM;

    float acc[TM][TN] = {};

    for (int kt = 0; kt < SEQ; kt += BK) {
        #pragma unroll
        for (int i = 0; i < 2; i++) {
            int idx = tid + i * THREADS;
            int row = idx / 4, c4 = idx % 4;
            float4 v = *(const float4*)(P + (size_t)(m0 + row) * SEQ + kt + c4 * 4);
            As[c4 * 4 + 0][row] = v.x;
            As[c4 * 4 + 1][row] = v.y;
            As[c4 * 4 + 2][row] = v.z;
            As[c4 * 4 + 3][row] = v.w;
        }
        {
            int row = tid / 16, c4 = tid % 16;
            *(float4*)&Bs[row][c4 * 4] =
                *(const float4*)(V + (size_t)(kt + row) * QKVN + c4 * 4);
        }
        __syncthreads();
        #pragma unroll
        for (int kk = 0; kk < BK; kk++) {
            float a[TM], bfr[TN];
            #pragma unroll
            for (int i = 0; i < TM; i += 4)
                *(float4*)&a[i] = *(float4*)&As[kk][ty * TM + i];
            *(float4*)&bfr[0] = *(float4*)&Bs[kk][tx * TN];
            #pragma unroll
            for (int i = 0; i < TM; i++)
                #pragma unroll
                for (int j = 0; j < TN; j++)
                    acc[i][j] += a[i] * bfr[j];
        }
        __syncthreads();
    }

    #pragma unroll
    for (int i = 0; i < TM; i++) {
        int m = m0 + ty * TM + i;
        float4 v;
        v.x = acc[i][0]; v.y = acc[i][1]; v.z = acc[i][2]; v.w = acc[i][3];
        *(float4*)(C + (size_t)m * DM + tx * TN) = v;
    }
}

// ---------------- host ----------------
extern "C" void kernel_launch(void* const* d_in, const int* in_sizes, int n_in,
                              void* d_out, int out_size) {
    const float* x    = (const float*)d_in[0];
    const float* Wqkv = (const float*)d_in[1];
    const float* bqkv = (const float*)d_in[2];
    const float* Wo   = (const float*)d_in[3];
    const float* bo   = (const float*)d_in[4];
    float* out = (float*)d_out;

    float *qkv, *scores, *attn;
    cudaGetSymbolAddress((void**)&qkv, g_qkv);
    cudaGetSymbolAddress((void**)&scores, g_scores);
    cudaGetSymbolAddress((void**)&attn, g_attn);

    // 1) qkv = x @ Wqkv + bqkv           [4096,2048]x[2048,3072]
    sgemm_bias<128, 128, 16, 8, 8>
        <<<dim3(QKVN / 128, MTOT / 128), 256>>>(x, Wqkv, bqkv, qkv, MTOT, QKVN, DM);

    // 2) S = Q K^T / sqrt(64)            batched 64x [2048,64]x[64,2048]
    score_kernel<<<dim3(SEQ / 128, SEQ / 128, BATCH * NQ), 256>>>(qkv, scores);

    // 3) row softmax
    softmax_kernel<<<dim3(SEQ, BATCH * NQ), 256>>>(scores);

    // 4) O = P V                          batched 64x [2048,2048]x[2048,64]
    pv_kernel<<<dim3(1, SEQ / 128, BATCH * NQ), 256>>>(scores, qkv, attn);

    // 5) out = O @ Wo + bo               [4096,2048]x[2048,2048]
    sgemm_bias<128, 128, 16, 8, 8>
        <<<dim3(DM / 128, MTOT / 128), 256>>>(attn, Wo, bo, out, MTOT, DM, DM);
}

// round 3
// speedup vs baseline: 2.4120x; 2.4120x over previous
#include <cuda_runtime.h>
#include <cuda_bf16.h>
#include <cstdint>

#define SEQ   2048
#define DM    2048
#define NQ    32
#define NKV   8
#define HD    64
#define QKVN  3072
#define BATCH 2
#define MTOT  (BATCH * SEQ)   // 4096
#define NHEAD (BATCH * NQ)    // 64

// ------------------------- scratch (device globals) -------------------------
__device__ __align__(128) __nv_bfloat16 g_xh[(size_t)MTOT * DM];
__device__ __align__(128) __nv_bfloat16 g_xl[(size_t)MTOT * DM];
__device__ __align__(128) __nv_bfloat16 g_wqth[(size_t)QKVN * DM];
__device__ __align__(128) __nv_bfloat16 g_wqtl[(size_t)QKVN * DM];
__device__ __align__(128) __nv_bfloat16 g_woth[(size_t)DM * DM];
__device__ __align__(128) __nv_bfloat16 g_wotl[(size_t)DM * DM];
__device__ __align__(128) __nv_bfloat16 g_qkvh[(size_t)MTOT * QKVN];
__device__ __align__(128) __nv_bfloat16 g_qkvl[(size_t)MTOT * QKVN];
__device__ __align__(128) __nv_bfloat16 g_vth[(size_t)BATCH * NKV * HD * SEQ];
__device__ __align__(128) __nv_bfloat16 g_vtl[(size_t)BATCH * NKV * HD * SEQ];
__device__ __align__(128) float         g_s[(size_t)NHEAD * SEQ * SEQ];
__device__ __align__(128) __nv_bfloat16 g_ph[(size_t)NHEAD * SEQ * SEQ];
__device__ __align__(128) __nv_bfloat16 g_pl[(size_t)NHEAD * SEQ * SEQ];
__device__ __align__(128) __nv_bfloat16 g_ah[(size_t)MTOT * DM];
__device__ __align__(128) __nv_bfloat16 g_al[(size_t)MTOT * DM];

// ------------------------- helpers ------------------------------------------
__device__ __forceinline__ uint32_t smem_u32(const void* p) {
    uint32_t a;
    asm("{ .reg .u64 t; cvta.to.shared.u64 t, %1; cvt.u32.u64 %0, t; }"
        : "=r"(a) : "l"(p));
    return a;
}

#define SMEM_SWIZZLE_128B(o) ((o) ^ (((o) >> 3) & 0x70))

__device__ __forceinline__ void cp16(uint32_t d, const void* s) {
    asm volatile("cp.async.cg.shared.global [%0], [%1], 16;" :: "r"(d), "l"(s));
}
#define CP_COMMIT() asm volatile("cp.async.commit_group;" ::: "memory")

#define LDSM4(R0, R1, R2, R3, A) \
    asm volatile("ldmatrix.sync.aligned.m8n8.x4.shared.b16 {%0,%1,%2,%3}, [%4];" \
                 : "=r"(R0), "=r"(R1), "=r"(R2), "=r"(R3) : "r"(A))
#define LDSM2(R0, R1, A) \
    asm volatile("ldmatrix.sync.aligned.m8n8.x2.shared.b16 {%0,%1}, [%2];" \
                 : "=r"(R0), "=r"(R1) : "r"(A))

#define MMA16816(C, A, B) \
    asm volatile("mma.sync.aligned.m16n8k16.row.col.f32.bf16.bf16.f32 " \
                 "{%0,%1,%2,%3}, {%4,%5,%6,%7}, {%8,%9}, {%0,%1,%2,%3};" \
                 : "+f"((C)[0]), "+f"((C)[1]), "+f"((C)[2]), "+f"((C)[3]) \
                 : "r"((A)[0]), "r"((A)[1]), "r"((A)[2]), "r"((A)[3]), \
                   "r"((B)[0]), "r"((B)[1]))

union B16x4 { uint2 v; __nv_bfloat16 b[4]; };

__device__ __forceinline__ void split2(float v, __nv_bfloat16& h, __nv_bfloat16& l) {
    h = __float2bfloat16(v);
    l = __float2bfloat16(v - __bfloat162float(h));
}

// ------------------------- mma.sync GEMM core --------------------------------
// acc[4][BN/32][4] += (Ah+Al)[128,K] @ ((Bh+Bl)[BN,K])^T  (3-term split)
// A/B row-major with K contiguous; lda/ldb in elements; K % 64 == 0.
template <int BN>
__device__ __forceinline__ void gemm_mma(
    char* smem, int tid,
    const __nv_bfloat16* __restrict__ Ah, const __nv_bfloat16* __restrict__ Al, int lda,
    const __nv_bfloat16* __restrict__ Bh, const __nv_bfloat16* __restrict__ Bl, int ldb,
    int K, float acc[4][BN / 32][4])
{
    constexpr int NT    = BN / 32;
    constexpr int ABY   = 128 * 128;  // bytes per A tensor stage (128 rows x 128B)
    constexpr int BBY   = BN * 128;
    constexpr int STAGE = 2 * ABY + 2 * BBY;

    const uint32_t su = smem_u32(smem);

    const int lane = tid & 31, warp = tid >> 5;
    const int wm = warp & 1, wn = warp >> 1;
    const int arow  = wm * 64 + (lane & 15);
    const int acolb = (lane >> 4) * 16;
    const int brow  = wn * (BN / 4) + (lane & 7);
    const int bcolb = ((lane >> 3) & 1) * 16;

    const int nch = K >> 6;

    auto issue = [&](int c) {
        const int k0 = c << 6;
        const uint32_t ub = su + (uint32_t)(c & 1) * STAGE;
        #pragma unroll
        for (int t = 0; t < 4; t++) {
            int i = tid + t * 256;
            int r = i >> 3, q = i & 7;
            uint32_t so = SMEM_SWIZZLE_128B((uint32_t)(r * 128 + q * 16));
            size_t off = (size_t)r * lda + k0 + q * 8;
            cp16(ub + so, Ah + off);
            cp16(ub + ABY + so, Al + off);
        }
        #pragma unroll
        for (int t = 0; t < (BN * 8) / 256; t++) {
            int i = tid + t * 256;
            int r = i >> 3, q = i & 7;
            uint32_t so = SMEM_SWIZZLE_128B((uint32_t)(r * 128 + q * 16));
            size_t off = (size_t)r * ldb + k0 + q * 8;
            cp16(ub + 2 * ABY + so, Bh + off);
            cp16(ub + 2 * ABY + BBY + so, Bl + off);
        }
        CP_COMMIT();
    };

    issue(0);
    for (int c = 0; c < nch; c++) {
        if (c + 1 < nch) {
            issue(c + 1);
            asm volatile("cp.async.wait_group 1;" ::: "memory");
        } else {
            asm volatile("cp.async.wait_group 0;" ::: "memory");
        }
        __syncthreads();
        const uint32_t ub = su + (uint32_t)(c & 1) * STAGE;
        #pragma unroll
        for (int ks = 0; ks < 4; ks++) {
            const int kb = ks * 32;
            uint32_t ahr[4][4], alr[4][4], bhr[NT][2], blr[NT][2];
            #pragma unroll
            for (int mt = 0; mt < 4; mt++) {
                uint32_t so = SMEM_SWIZZLE_128B(
                    (uint32_t)((arow + mt * 16) * 128 + kb + acolb));
                LDSM4(ahr[mt][0], ahr[mt][1], ahr[mt][2], ahr[mt][3], ub + so);
                LDSM4(alr[mt][0], alr[mt][1], alr[mt][2], alr[mt][3], ub + ABY + so);
            }
            #pragma unroll
            for (int nt = 0; nt < NT; nt++) {
                uint32_t so = SMEM_SWIZZLE_128B(
                    (uint32_t)((brow + nt * 8) * 128 + kb + bcolb));
                LDSM2(bhr[nt][0], bhr[nt][1], ub + 2 * ABY + so);
                LDSM2(blr[nt][0], blr[nt][1], ub + 2 * ABY + BBY + so);
            }
            #pragma unroll
            for (int mt = 0; mt < 4; mt++)
                #pragma unroll
                for (int nt = 0; nt < NT; nt++) {
                    MMA16816(acc[mt][nt], ahr[mt], bhr[nt]);
                    MMA16816(acc[mt][nt], ahr[mt], blr[nt]);
                    MMA16816(acc[mt][nt], alr[mt], bhr[nt]);
                }
        }
        __syncthreads();
    }
}

static constexpr int SMEM_G128 = 2 * (2 * 128 * 128 + 2 * 128 * 128);  // 131072
static constexpr int SMEM_G64  = 2 * (2 * 128 * 128 + 2 * 64 * 128);   //  98304

// ------------------------- prep kernels -------------------------------------
__global__ __launch_bounds__(256) void k_split(const float* __restrict__ x,
                                               __nv_bfloat16* __restrict__ xh,
                                               __nv_bfloat16* __restrict__ xl) {
    size_t i = ((size_t)blockIdx.x * 256 + threadIdx.x) * 4;
    float4 v = *(const float4*)(x + i);
    B16x4 h, l;
    split2(v.x, h.b[0], l.b[0]); split2(v.y, h.b[1], l.b[1]);
    split2(v.z, h.b[2], l.b[2]); split2(v.w, h.b[3], l.b[3]);
    *(uint2*)(xh + i) = h.v;
    *(uint2*)(xl + i) = l.v;
}

// W [K,N] fp32 -> Th/Tl [N,K] bf16
__global__ __launch_bounds__(256) void k_tsplit(const float* __restrict__ W,
                                                __nv_bfloat16* __restrict__ Th,
                                                __nv_bfloat16* __restrict__ Tl,
                                                int K, int N) {
    __shared__ float t[32][33];
    const int n0 = blockIdx.x * 32, k0 = blockIdx.y * 32;
    const int tx = threadIdx.x, ty = threadIdx.y;
    #pragma unroll
    for (int i = 0; i < 4; i++)
        t[ty * 4 + i][tx] = W[(size_t)(k0 + ty * 4 + i) * N + n0 + tx];
    __syncthreads();
    #pragma unroll
    for (int i = 0; i < 4; i++) {
        float v = t[tx][ty * 4 + i];
        __nv_bfloat16 h, l; split2(v, h, l);
        size_t o = (size_t)(n0 + ty * 4 + i) * K + k0 + tx;
        Th[o] = h; Tl[o] = l;
    }
}

// V region of qkv (bf16 hi/lo) -> Vt [b*NKV+kv][HD][SEQ]
__global__ __launch_bounds__(256) void k_vt(const __nv_bfloat16* __restrict__ qh,
                                            const __nv_bfloat16* __restrict__ ql,
                                            __nv_bfloat16* __restrict__ vth,
                                            __nv_bfloat16* __restrict__ vtl) {
    __shared__ __nv_bfloat16 th[32][33], tl[32][33];
    const int bk = blockIdx.z, b = bk >> 3, kv = bk & 7;
    const int s0 = blockIdx.x * 32, n0 = blockIdx.y * 32;
    const int tx = threadIdx.x, ty = threadIdx.y;
    #pragma unroll
    for (int i = 0; i < 4; i++) {
        size_t src = ((size_t)b * SEQ + s0 + ty * 4 + i) * QKVN + (NQ + NKV) * HD + kv * HD + n0 + tx;
        th[ty * 4 + i][tx] = qh[src];
        tl[ty * 4 + i][tx] = ql[src];
    }
    __syncthreads();
    #pragma unroll
    for (int i = 0; i < 4; i++) {
        size_t dst = ((size_t)bk * HD + n0 + ty * 4 + i) * SEQ + s0 + tx;
        vth[dst] = th[tx][ty * 4 + i];
        vtl[dst] = tl[tx][ty * 4 + i];
    }
}

// ------------------------- GEMM kernels -------------------------------------
__global__ __launch_bounds__(256, 1) void k_gemm_qkv(
    const __nv_bfloat16* __restrict__ xh, const __nv_bfloat16* __restrict__ xl,
    const __nv_bfloat16* __restrict__ wth, const __nv_bfloat16* __restrict__ wtl,
    const float* __restrict__ bias,
    __nv_bfloat16* __restrict__ qh, __nv_bfloat16* __restrict__ ql) {
    extern __shared__ char smem[];
    const int tid = threadIdx.x;
    const size_t m0 = (size_t)blockIdx.y * 128, n0 = (size_t)blockIdx.x * 128;
    float acc[4][4][4] = {};
    gemm_mma<128>(smem, tid, xh + m0 * DM, xl + m0 * DM, DM,
                  wth + n0 * DM, wtl + n0 * DM, DM, DM, acc);
    const int lane = tid & 31, warp = tid >> 5;
    const int wm = warp & 1, wn = warp >> 1;
    const int g = lane >> 2, tg = lane & 3;
    #pragma unroll
    for (int mt = 0; mt < 4; mt++)
        #pragma unroll
        for (int half = 0; half < 2; half++) {
            const size_t m = m0 + wm * 64 + mt * 16 + g + half * 8;
            #pragma unroll
            for (int nt = 0; nt < 4; nt++) {
                const int nl = wn * 32 + nt * 8 + tg * 2;
                float v0 = acc[mt][nt][half * 2 + 0] + bias[n0 + nl];
                float v1 = acc[mt][nt][half * 2 + 1] + bias[n0 + nl + 1];
                __nv_bfloat162 hp, lp;
                split2(v0, hp.x, lp.x);
                split2(v1, hp.y, lp.y);
                *(__nv_bfloat162*)(qh + m * QKVN + n0 + nl) = hp;
                *(__nv_bfloat162*)(ql + m * QKVN + n0 + nl) = lp;
            }
        }
}

__global__ __launch_bounds__(256, 1) void k_score(
    const __nv_bfloat16* __restrict__ qh, const __nv_bfloat16* __restrict__ ql,
    float* __restrict__ sc) {
    extern __shared__ char smem[];
    const int tid = threadIdx.x;
    const int z = blockIdx.z, b = z >> 5, h = z & 31;
    const size_t m0 = (size_t)blockIdx.y * 128, n0 = (size_t)blockIdx.x * 128;
    const size_t aoff = ((size_t)b * SEQ + m0) * QKVN + h * HD;
    const size_t boff = ((size_t)b * SEQ + n0) * QKVN + NQ * HD + (h >> 2) * HD;
    float acc[4][4][4] = {};
    gemm_mma<128>(smem, tid, qh + aoff, ql + aoff, QKVN,
                  qh + boff, ql + boff, QKVN, HD, acc);
    const int lane = tid & 31, warp = tid >> 5;
    const int wm = warp & 1, wn = warp >> 1;
    const int g = lane >> 2, tg = lane & 3;
    #pragma unroll
    for (int mt = 0; mt < 4; mt++)
        #pragma unroll
        for (int half = 0; half < 2; half++) {
            const size_t m = m0 + wm * 64 + mt * 16 + g + half * 8;
            float* dst = sc + ((size_t)z * SEQ + m) * SEQ + n0;
            #pragma unroll
            for (int nt = 0; nt < 4; nt++) {
                const int nl = wn * 32 + nt * 8 + tg * 2;
                float2 v;
                v.x = acc[mt][nt][half * 2 + 0] * 0.125f;
                v.y = acc[mt][nt][half * 2 + 1] * 0.125f;
                *(float2*)(dst + nl) = v;
            }
        }
}

__global__ __launch_bounds__(256, 1) void k_pv(
    const __nv_bfloat16* __restrict__ ph, const __nv_bfloat16* __restrict__ pl,
    const __nv_bfloat16* __restrict__ vth, const __nv_bfloat16* __restrict__ vtl,
    __nv_bfloat16* __restrict__ ah, __nv_bfloat16* __restrict__ al) {
    extern __shared__ char smem[];
    const int tid = threadIdx.x;
    const int z = blockIdx.z, b = z >> 5, h = z & 31;
    const size_t m0 = (size_t)blockIdx.y * 128;
    const size_t aoff = ((size_t)z * SEQ + m0) * SEQ;
    const size_t boff = (size_t)(b * NKV + (h >> 2)) * HD * SEQ;
    float acc[4][2][4] = {};
    gemm_mma<64>(smem, tid, ph + aoff, pl + aoff, SEQ,
                 vth + boff, vtl + boff, SEQ, SEQ, acc);
    const int lane = tid & 31, warp = tid >> 5;
    const int wm = warp & 1, wn = warp >> 1;
    const int g = lane >> 2, tg = lane & 3;
    #pragma unroll
    for (int mt = 0; mt < 4; mt++)
        #pragma unroll
        for (int half = 0; half < 2; half++) {
            const size_t m = m0 + wm * 64 + mt * 16 + g + half * 8;
            const size_t row = ((size_t)b * SEQ + m) * DM + h * HD;
            #pragma unroll
            for (int nt = 0; nt < 2; nt++) {
                const int nl = wn * 16 + nt * 8 + tg * 2;
                __nv_bfloat162 hp, lp;
                split2(acc[mt][nt][half * 2 + 0], hp.x, lp.x);
                split2(acc[mt][nt][half * 2 + 1], hp.y, lp.y);
                *(__nv_bfloat162*)(ah + row + nl) = hp;
                *(__nv_bfloat162*)(al + row + nl) = lp;
            }
        }
}

__global__ __launch_bounds__(256, 1) void k_proj(
    const __nv_bfloat16* __restrict__ ah, const __nv_bfloat16* __restrict__ al,
    const __nv_bfloat16* __restrict__ wth, const __nv_bfloat16* __restrict__ wtl,
    const float* __restrict__ bias, float* __restrict__ out) {
    extern __shared__ char smem[];
    const int tid = threadIdx.x;
    const size_t m0 = (size_t)blockIdx.y * 128, n0 = (size_t)blockIdx.x * 128;
    float acc[4][4][4] = {};
    gemm_mma<128>(smem, tid, ah + m0 * DM, al + m0 * DM, DM,
                  wth + n0 * DM, wtl + n0 * DM, DM, DM, acc);
    const int lane = tid & 31, warp = tid >> 5;
    const int wm = warp & 1, wn = warp >> 1;
    const int g = lane >> 2, tg = lane & 3;
    #pragma unroll
    for (int mt = 0; mt < 4; mt++)
        #pragma unroll
        for (int half = 0; half < 2; half++) {
            const size_t m = m0 + wm * 64 + mt * 16 + g + half * 8;
            float* dst = out + m * DM + n0;
            #pragma unroll
            for (int nt = 0; nt < 4; nt++) {
                const int nl = wn * 32 + nt * 8 + tg * 2;
                float2 v;
                v.x = acc[mt][nt][half * 2 + 0] + bias[n0 + nl];
                v.y = acc[mt][nt][half * 2 + 1] + bias[n0 + nl + 1];
                *(float2*)(dst + nl) = v;
            }
        }
}

// ------------------------- softmax ------------------------------------------
__global__ __launch_bounds__(256) void k_softmax(const float* __restrict__ sc,
                                                 __nv_bfloat16* __restrict__ ph,
                                                 __nv_bfloat16* __restrict__ pl) {
    const size_t row = (size_t)blockIdx.y * SEQ + blockIdx.x;
    const float4* p = (const float4*)(sc + row * SEQ);
    const int tid = threadIdx.x;
    __shared__ float red_m[8], red_s[8];

    float4 v0 = p[tid];
    float4 v1 = p[tid + 256];

    float m = fmaxf(fmaxf(fmaxf(v0.x, v0.y), fmaxf(v0.z, v0.w)),
                    fmaxf(fmaxf(v1.x, v1.y), fmaxf(v1.z, v1.w)));
    #pragma unroll
    for (int o = 16; o; o >>= 1) m = fmaxf(m, __shfl_xor_sync(0xffffffffu, m, o));
    if ((tid & 31) == 0) red_m[tid >> 5] = m;
    __syncthreads();
    m = fmaxf(fmaxf(fmaxf(red_m[0], red_m[1]), fmaxf(red_m[2], red_m[3])),
              fmaxf(fmaxf(red_m[4], red_m[5]), fmaxf(red_m[6], red_m[7])));

    v0.x = __expf(v0.x - m); v0.y = __expf(v0.y - m);
    v0.z = __expf(v0.z - m); v0.w = __expf(v0.w - m);
    v1.x = __expf(v1.x - m); v1.y = __expf(v1.y - m);
    v1.z = __expf(v1.z - m); v1.w = __expf(v1.w - m);

    float s = (v0.x + v0.y) + (v0.z + v0.w) + (v1.x + v1.y) + (v1.z + v1.w);
    #pragma unroll
    for (int o = 16; o; o >>= 1) s += __shfl_xor_sync(0xffffffffu, s, o);
    if ((tid & 31) == 0) red_s[tid >> 5] = s;
    __syncthreads();
    s = (red_s[0] + red_s[1]) + (red_s[2] + red_s[3]) +
        (red_s[4] + red_s[5]) + (red_s[6] + red_s[7]);

    const float inv = 1.0f / s;
    B16x4 h4, l4;
    split2(v0.x * inv, h4.b[0], l4.b[0]); split2(v0.y * inv, h4.b[1], l4.b[1]);
    split2(v0.z * inv, h4.b[2], l4.b[2]); split2(v0.w * inv, h4.b[3], l4.b[3]);
    *(uint2*)(ph + row * SEQ + tid * 4) = h4.v;
    *(uint2*)(pl + row * SEQ + tid * 4) = l4.v;
    split2(v1.x * inv, h4.b[0], l4.b[0]); split2(v1.y * inv, h4.b[1], l4.b[1]);
    split2(v1.z * inv, h4.b[2], l4.b[2]); split2(v1.w * inv, h4.b[3], l4.b[3]);
    *(uint2*)(ph + row * SEQ + (tid + 256) * 4) = h4.v;
    *(uint2*)(pl + row * SEQ + (tid + 256) * 4) = l4.v;
}

// ------------------------- host ---------------------------------------------
extern "C" void kernel_launch(void* const* d_in, const int* in_sizes, int n_in,
                              void* d_out, int out_size) {
    const float* x    = (const float*)d_in[0];
    const float* Wqkv = (const float*)d_in[1];
    const float* bqkv = (const float*)d_in[2];
    const float* Wo   = (const float*)d_in[3];
    const float* bo   = (const float*)d_in[4];
    float* out = (float*)d_out;

    __nv_bfloat16 *xh, *xl, *wqth, *wqtl, *woth, *wotl, *qkvh, *qkvl;
    __nv_bfloat16 *vth, *vtl, *ph, *pl, *ah, *al;
    float* sc;
    cudaGetSymbolAddress((void**)&xh, g_xh);     cudaGetSymbolAddress((void**)&xl, g_xl);
    cudaGetSymbolAddress((void**)&wqth, g_wqth); cudaGetSymbolAddress((void**)&wqtl, g_wqtl);
    cudaGetSymbolAddress((void**)&woth, g_woth); cudaGetSymbolAddress((void**)&wotl, g_wotl);
    cudaGetSymbolAddress((void**)&qkvh, g_qkvh); cudaGetSymbolAddress((void**)&qkvl, g_qkvl);
    cudaGetSymbolAddress((void**)&vth, g_vth);   cudaGetSymbolAddress((void**)&vtl, g_vtl);
    cudaGetSymbolAddress((void**)&sc, g_s);
    cudaGetSymbolAddress((void**)&ph, g_ph);     cudaGetSymbolAddress((void**)&pl, g_pl);
    cudaGetSymbolAddress((void**)&ah, g_ah);     cudaGetSymbolAddress((void**)&al, g_al);

    cudaFuncSetAttribute(k_gemm_qkv, cudaFuncAttributeMaxDynamicSharedMemorySize, SMEM_G128);
    cudaFuncSetAttribute(k_score,    cudaFuncAttributeMaxDynamicSharedMemorySize, SMEM_G128);
    cudaFuncSetAttribute(k_pv,       cudaFuncAttributeMaxDynamicSharedMemorySize, SMEM_G64);
    cudaFuncSetAttribute(k_proj,     cudaFuncAttributeMaxDynamicSharedMemorySize, SMEM_G128);

    // prep: split x, transpose+split weights
    k_split<<<(size_t)MTOT * DM / 1024, 256>>>(x, xh, xl);
    k_tsplit<<<dim3(QKVN / 32, DM / 32), dim3(32, 8)>>>(Wqkv, wqth, wqtl, DM, QKVN);
    k_tsplit<<<dim3(DM / 32, DM / 32), dim3(32, 8)>>>(Wo, woth, wotl, DM, DM);

    // 1) qkv = x @ Wqkv + b  (emit bf16 hi/lo)
    k_gemm_qkv<<<dim3(QKVN / 128, MTOT / 128), 256, SMEM_G128>>>(
        xh, xl, wqth, wqtl, bqkv, qkvh, qkvl);

    // V transpose for PV's B operand
    k_vt<<<dim3(SEQ / 32, HD / 32, BATCH * NKV), dim3(32, 8)>>>(qkvh, qkvl, vth, vtl);

    // 2) S = Q K^T / 8
    k_score<<<dim3(SEQ / 128, SEQ / 128, NHEAD), 256, SMEM_G128>>>(qkvh, qkvl, sc);

    // 3) softmax -> P hi/lo
    k_softmax<<<dim3(SEQ, NHEAD), 256>>>(sc, ph, pl);

    // 4) O = P V (emit bf16 hi/lo)
    k_pv<<<dim3(1, SEQ / 128, NHEAD), 256, SMEM_G64>>>(ph, pl, vth, vtl, ah, al);

    // 5) out = O @ Wo + b
    k_proj<<<dim3(DM / 128, MTOT / 128), 256, SMEM_G128>>>(ah, al, woth, wotl, bo, out);
}

// round 5
// speedup vs baseline: 3.4744x; 1.4405x over previous
#include <cuda_runtime.h>
#include <cuda_bf16.h>
#include <cstdint>

#define SEQ   2048
#define DM    2048
#define NQ    32
#define NKV   8
#define HD    64
#define QKVN  3072
#define BATCH 2
#define MTOT  (BATCH * SEQ)   // 4096
#define NHEAD (BATCH * NQ)    // 64

// ------------------------- scratch (device globals) -------------------------
__device__ __align__(128) __nv_bfloat16 g_xh[(size_t)MTOT * DM];
__device__ __align__(128) __nv_bfloat16 g_xl[(size_t)MTOT * DM];
__device__ __align__(128) __nv_bfloat16 g_wqth[(size_t)QKVN * DM];
__device__ __align__(128) __nv_bfloat16 g_wqtl[(size_t)QKVN * DM];
__device__ __align__(128) __nv_bfloat16 g_woth[(size_t)DM * DM];
__device__ __align__(128) __nv_bfloat16 g_wotl[(size_t)DM * DM];
__device__ __align__(128) __nv_bfloat16 g_qkvh[(size_t)MTOT * QKVN];
__device__ __align__(128) __nv_bfloat16 g_qkvl[(size_t)MTOT * QKVN];
__device__ __align__(128) __nv_bfloat16 g_vth[(size_t)BATCH * NKV * HD * SEQ];
__device__ __align__(128) __nv_bfloat16 g_vtl[(size_t)BATCH * NKV * HD * SEQ];
__device__ __align__(128) __nv_bfloat16 g_ah[(size_t)MTOT * DM];
__device__ __align__(128) __nv_bfloat16 g_al[(size_t)MTOT * DM];

// ------------------------- helpers ------------------------------------------
__device__ __forceinline__ uint32_t smem_u32(const void* p) {
    uint32_t a;
    asm("{ .reg .u64 t; cvta.to.shared.u64 t, %1; cvt.u32.u64 %0, t; }"
        : "=r"(a) : "l"(p));
    return a;
}

#define SMEM_SWIZZLE_128B(o) ((o) ^ (((o) >> 3) & 0x70))

__device__ __forceinline__ void cp16(uint32_t d, const void* s) {
    asm volatile("cp.async.cg.shared.global [%0], [%1], 16;" :: "r"(d), "l"(s));
}
#define CP_COMMIT() asm volatile("cp.async.commit_group;" ::: "memory")

#define LDSM4(R0, R1, R2, R3, A) \
    asm volatile("ldmatrix.sync.aligned.m8n8.x4.shared.b16 {%0,%1,%2,%3}, [%4];" \
                 : "=r"(R0), "=r"(R1), "=r"(R2), "=r"(R3) : "r"(A))
#define LDSM2(R0, R1, A) \
    asm volatile("ldmatrix.sync.aligned.m8n8.x2.shared.b16 {%0,%1}, [%2];" \
                 : "=r"(R0), "=r"(R1) : "r"(A))

#define MMA16816(C, A, B) \
    asm volatile("mma.sync.aligned.m16n8k16.row.col.f32.bf16.bf16.f32 " \
                 "{%0,%1,%2,%3}, {%4,%5,%6,%7}, {%8,%9}, {%0,%1,%2,%3};" \
                 : "+f"((C)[0]), "+f"((C)[1]), "+f"((C)[2]), "+f"((C)[3]) \
                 : "r"((A)[0]), "r"((A)[1]), "r"((A)[2]), "r"((A)[3]), \
                   "r"((B)[0]), "r"((B)[1]))

union B16x4 { uint2 v; __nv_bfloat16 b[4]; };

__device__ __forceinline__ void split2(float v, __nv_bfloat16& h, __nv_bfloat16& l) {
    h = __float2bfloat16(v);
    l = __float2bfloat16(v - __bfloat162float(h));
}
// pack (a,b) into hi-bf16x2 and lo-bf16x2 words
__device__ __forceinline__ void pk2split(float a, float b, uint32_t& hi, uint32_t& lo) {
    __nv_bfloat162 h, l;
    split2(a, h.x, l.x);
    split2(b, h.y, l.y);
    hi = *(uint32_t*)&h;
    lo = *(uint32_t*)&l;
}

// ------------------------- mma.sync GEMM core (BN=128) ----------------------
__device__ __forceinline__ void gemm_mma128(
    char* smem, int tid,
    const __nv_bfloat16* __restrict__ Ah, const __nv_bfloat16* __restrict__ Al, int lda,
    const __nv_bfloat16* __restrict__ Bh, const __nv_bfloat16* __restrict__ Bl, int ldb,
    int K, float acc[4][4][4])
{
    constexpr int ABY   = 128 * 128;
    constexpr int BBY   = 128 * 128;
    constexpr int STAGE = 2 * ABY + 2 * BBY;

    const uint32_t su = smem_u32(smem);
    const int lane = tid & 31, warp = tid >> 5;
    const int wm = warp & 1, wn = warp >> 1;
    const int arow  = wm * 64 + (lane & 15);
    const int acolb = (lane >> 4) * 16;
    const int brow  = wn * 32 + (lane & 7);
    const int bcolb = ((lane >> 3) & 1) * 16;
    const int nch = K >> 6;

    auto issue = [&](int c) {
        const int k0 = c << 6;
        const uint32_t ub = su + (uint32_t)(c & 1) * STAGE;
        #pragma unroll
        for (int t = 0; t < 4; t++) {
            int i = tid + t * 256;
            int r = i >> 3, q = i & 7;
            uint32_t so = SMEM_SWIZZLE_128B((uint32_t)(r * 128 + q * 16));
            size_t off = (size_t)r * lda + k0 + q * 8;
            cp16(ub + so, Ah + off);
            cp16(ub + ABY + so, Al + off);
        }
        #pragma unroll
        for (int t = 0; t < 4; t++) {
            int i = tid + t * 256;
            int r = i >> 3, q = i & 7;
            uint32_t so = SMEM_SWIZZLE_128B((uint32_t)(r * 128 + q * 16));
            size_t off = (size_t)r * ldb + k0 + q * 8;
            cp16(ub + 2 * ABY + so, Bh + off);
            cp16(ub + 2 * ABY + BBY + so, Bl + off);
        }
        CP_COMMIT();
    };

    issue(0);
    for (int c = 0; c < nch; c++) {
        if (c + 1 < nch) {
            issue(c + 1);
            asm volatile("cp.async.wait_group 1;" ::: "memory");
        } else {
            asm volatile("cp.async.wait_group 0;" ::: "memory");
        }
        __syncthreads();
        const uint32_t ub = su + (uint32_t)(c & 1) * STAGE;
        #pragma unroll
        for (int ks = 0; ks < 4; ks++) {
            const int kb = ks * 32;
            uint32_t ahr[4][4], alr[4][4], bhr[4][2], blr[4][2];
            #pragma unroll
            for (int mt = 0; mt < 4; mt++) {
                uint32_t so = SMEM_SWIZZLE_128B(
                    (uint32_t)((arow + mt * 16) * 128 + kb + acolb));
                LDSM4(ahr[mt][0], ahr[mt][1], ahr[mt][2], ahr[mt][3], ub + so);
                LDSM4(alr[mt][0], alr[mt][1], alr[mt][2], alr[mt][3], ub + ABY + so);
            }
            #pragma unroll
            for (int nt = 0; nt < 4; nt++) {
                uint32_t so = SMEM_SWIZZLE_128B(
                    (uint32_t)((brow + nt * 8) * 128 + kb + bcolb));
                LDSM2(bhr[nt][0], bhr[nt][1], ub + 2 * ABY + so);
                LDSM2(blr[nt][0], blr[nt][1], ub + 2 * ABY + BBY + so);
            }
            #pragma unroll
            for (int mt = 0; mt < 4; mt++)
                #pragma unroll
                for (int nt = 0; nt < 4; nt++) {
                    MMA16816(acc[mt][nt], ahr[mt], bhr[nt]);
                    MMA16816(acc[mt][nt], ahr[mt], blr[nt]);
                    MMA16816(acc[mt][nt], alr[mt], bhr[nt]);
                }
        }
        __syncthreads();
    }
}

static constexpr int SMEM_G128 = 2 * (2 * 128 * 128 + 2 * 128 * 128);  // 131072
static constexpr int SMEM_FL   = 32768 + 2 * 65536;                    // 163840

// ------------------------- prep kernels -------------------------------------
__global__ __launch_bounds__(256) void k_split(const float* __restrict__ x,
                                               __nv_bfloat16* __restrict__ xh,
                                               __nv_bfloat16* __restrict__ xl) {
    size_t i = ((size_t)blockIdx.x * 256 + threadIdx.x) * 4;
    float4 v = *(const float4*)(x + i);
    B16x4 h, l;
    split2(v.x, h.b[0], l.b[0]); split2(v.y, h.b[1], l.b[1]);
    split2(v.z, h.b[2], l.b[2]); split2(v.w, h.b[3], l.b[3]);
    *(uint2*)(xh + i) = h.v;
    *(uint2*)(xl + i) = l.v;
}

__global__ __launch_bounds__(256) void k_tsplit(const float* __restrict__ W,
                                                __nv_bfloat16* __restrict__ Th,
                                                __nv_bfloat16* __restrict__ Tl,
                                                int K, int N) {
    __shared__ float t[32][33];
    const int n0 = blockIdx.x * 32, k0 = blockIdx.y * 32;
    const int tx = threadIdx.x, ty = threadIdx.y;
    #pragma unroll
    for (int i = 0; i < 4; i++)
        t[ty * 4 + i][tx] = W[(size_t)(k0 + ty * 4 + i) * N + n0 + tx];
    __syncthreads();
    #pragma unroll
    for (int i = 0; i < 4; i++) {
        float v = t[tx][ty * 4 + i];
        __nv_bfloat16 h, l; split2(v, h, l);
        size_t o = (size_t)(n0 + ty * 4 + i) * K + k0 + tx;
        Th[o] = h; Tl[o] = l;
    }
}

__global__ __launch_bounds__(256) void k_vt(const __nv_bfloat16* __restrict__ qh,
                                            const __nv_bfloat16* __restrict__ ql,
                                            __nv_bfloat16* __restrict__ vth,
                                            __nv_bfloat16* __restrict__ vtl) {
    __shared__ __nv_bfloat16 th[32][33], tl[32][33];
    const int bk = blockIdx.z, b = bk >> 3, kv = bk & 7;
    const int s0 = blockIdx.x * 32, n0 = blockIdx.y * 32;
    const int tx = threadIdx.x, ty = threadIdx.y;
    #pragma unroll
    for (int i = 0; i < 4; i++) {
        size_t src = ((size_t)b * SEQ + s0 + ty * 4 + i) * QKVN + (NQ + NKV) * HD + kv * HD + n0 + tx;
        th[ty * 4 + i][tx] = qh[src];
        tl[ty * 4 + i][tx] = ql[src];
    }
    __syncthreads();
    #pragma unroll
    for (int i = 0; i < 4; i++) {
        size_t dst = ((size_t)bk * HD + n0 + ty * 4 + i) * SEQ + s0 + tx;
        vth[dst] = th[tx][ty * 4 + i];
        vtl[dst] = tl[tx][ty * 4 + i];
    }
}

// ------------------------- GEMM kernels (qkv, proj) -------------------------
__global__ __launch_bounds__(256, 1) void k_gemm_qkv(
    const __nv_bfloat16* __restrict__ xh, const __nv_bfloat16* __restrict__ xl,
    const __nv_bfloat16* __restrict__ wth, const __nv_bfloat16* __restrict__ wtl,
    const float* __restrict__ bias,
    __nv_bfloat16* __restrict__ qh, __nv_bfloat16* __restrict__ ql) {
    extern __shared__ char smem[];
    const int tid = threadIdx.x;
    const size_t m0 = (size_t)blockIdx.y * 128, n0 = (size_t)blockIdx.x * 128;
    float acc[4][4][4] = {};
    gemm_mma128(smem, tid, xh + m0 * DM, xl + m0 * DM, DM,
                wth + n0 * DM, wtl + n0 * DM, DM, DM, acc);
    const int lane = tid & 31, warp = tid >> 5;
    const int wm = warp & 1, wn = warp >> 1;
    const int g = lane >> 2, tg = lane & 3;
    #pragma unroll
    for (int mt = 0; mt < 4; mt++)
        #pragma unroll
        for (int half = 0; half < 2; half++) {
            const size_t m = m0 + wm * 64 + mt * 16 + g + half * 8;
            #pragma unroll
            for (int nt = 0; nt < 4; nt++) {
                const int nl = wn * 32 + nt * 8 + tg * 2;
                float v0 = acc[mt][nt][half * 2 + 0] + bias[n0 + nl];
                float v1 = acc[mt][nt][half * 2 + 1] + bias[n0 + nl + 1];
                __nv_bfloat162 hp, lp;
                split2(v0, hp.x, lp.x);
                split2(v1, hp.y, lp.y);
                *(__nv_bfloat162*)(qh + m * QKVN + n0 + nl) = hp;
                *(__nv_bfloat162*)(ql + m * QKVN + n0 + nl) = lp;
            }
        }
}

__global__ __launch_bounds__(256, 1) void k_proj(
    const __nv_bfloat16* __restrict__ ah, const __nv_bfloat16* __restrict__ al,
    const __nv_bfloat16* __restrict__ wth, const __nv_bfloat16* __restrict__ wtl,
    const float* __restrict__ bias, float* __restrict__ out) {
    extern __shared__ char smem[];
    const int tid = threadIdx.x;
    const size_t m0 = (size_t)blockIdx.y * 128, n0 = (size_t)blockIdx.x * 128;
    float acc[4][4][4] = {};
    gemm_mma128(smem, tid, ah + m0 * DM, al + m0 * DM, DM,
                wth + n0 * DM, wtl + n0 * DM, DM, DM, acc);
    const int lane = tid & 31, warp = tid >> 5;
    const int wm = warp & 1, wn = warp >> 1;
    const int g = lane >> 2, tg = lane & 3;
    #pragma unroll
    for (int mt = 0; mt < 4; mt++)
        #pragma unroll
        for (int half = 0; half < 2; half++) {
            const size_t m = m0 + wm * 64 + mt * 16 + g + half * 8;
            float* dst = out + m * DM + n0;
            #pragma unroll
            for (int nt = 0; nt < 4; nt++) {
                const int nl = wn * 32 + nt * 8 + tg * 2;
                float2 v;
                v.x = acc[mt][nt][half * 2 + 0] + bias[n0 + nl];
                v.y = acc[mt][nt][half * 2 + 1] + bias[n0 + nl + 1];
                *(float2*)(dst + nl) = v;
            }
        }
}

// ------------------------- fused flash attention ----------------------------
// Grid (SEQ/128, NHEAD). 8 warps, warp w owns Q rows [w*16, w*16+16).
// smem: QH 0, QL 16K; stage s at 32K + s*64K: {KH, KL, VH, VL} x 16K.
// V stage layout: Vt[d=0..63][k half][k%64] — each 64x64 half SW128-swizzled.
__global__ __launch_bounds__(256, 1) void k_flash(
    const __nv_bfloat16* __restrict__ qkvh, const __nv_bfloat16* __restrict__ qkvl,
    const __nv_bfloat16* __restrict__ vth, const __nv_bfloat16* __restrict__ vtl,
    __nv_bfloat16* __restrict__ ah, __nv_bfloat16* __restrict__ al)
{
    extern __shared__ char smem[];
    const uint32_t su = smem_u32(smem);
    const int tid = threadIdx.x, lane = tid & 31, w = tid >> 5;
    const int z = blockIdx.y, b = z >> 5, h = z & 31, kvh = h >> 2;
    const int m0 = blockIdx.x * 128;

    const __nv_bfloat16* Qh = qkvh + ((size_t)(b * SEQ + m0)) * QKVN + h * HD;
    const __nv_bfloat16* Ql = qkvl + ((size_t)(b * SEQ + m0)) * QKVN + h * HD;
    const __nv_bfloat16* Kh = qkvh + (size_t)b * SEQ * QKVN + NQ * HD + kvh * HD;
    const __nv_bfloat16* Kl = qkvl + (size_t)b * SEQ * QKVN + NQ * HD + kvh * HD;
    const __nv_bfloat16* Vh = vth + (size_t)(b * NKV + kvh) * HD * SEQ;
    const __nv_bfloat16* Vl = vtl + (size_t)(b * NKV + kvh) * HD * SEQ;

    // Q tile load (group 0)
    #pragma unroll
    for (int t = 0; t < 4; t++) {
        int i = tid + t * 256;
        int r = i >> 3, q = i & 7;
        uint32_t so = SMEM_SWIZZLE_128B((uint32_t)(r * 128 + q * 16));
        size_t off = (size_t)r * QKVN + q * 8;
        cp16(su + so, Qh + off);
        cp16(su + 16384 + so, Ql + off);
    }
    CP_COMMIT();

    auto issue_kv = [&](int kt) {
        uint32_t ub = su + 32768 + (uint32_t)(kt & 1) * 65536;
        #pragma unroll
        for (int t = 0; t < 4; t++) {
            int i = tid + t * 256;
            int r = i >> 3, q = i & 7;
            uint32_t so = SMEM_SWIZZLE_128B((uint32_t)(r * 128 + q * 16));
            size_t off = (size_t)(kt * 128 + r) * QKVN + q * 8;
            cp16(ub + so, Kh + off);
            cp16(ub + 16384 + so, Kl + off);
        }
        #pragma unroll
        for (int t = 0; t < 4; t++) {
            int i = tid + t * 256;
            int d = i >> 4, q = i & 15;
            uint32_t so = (uint32_t)(q >> 3) * 8192 +
                          SMEM_SWIZZLE_128B((uint32_t)(d * 128 + (q & 7) * 16));
            size_t off = (size_t)d * SEQ + kt * 128 + q * 8;
            cp16(ub + 32768 + so, Vh + off);
            cp16(ub + 49152 + so, Vl + off);
        }
        CP_COMMIT();
    };

    issue_kv(0);
    asm volatile("cp.async.wait_group 1;" ::: "memory");  // Q done
    __syncthreads();

    // Q fragments (persistent)
    uint32_t qhf[4][4], qlf[4][4];
    {
        const int arow = w * 16 + (lane & 15);
        const int acolb = (lane >> 4) * 16;
        #pragma unroll
        for (int ks = 0; ks < 4; ks++) {
            uint32_t so = SMEM_SWIZZLE_128B((uint32_t)(arow * 128 + ks * 32 + acolb));
            LDSM4(qhf[ks][0], qhf[ks][1], qhf[ks][2], qhf[ks][3], su + so);
            LDSM4(qlf[ks][0], qlf[ks][1], qlf[ks][2], qlf[ks][3], su + 16384 + so);
        }
    }

    float accO[8][4] = {};
    float mr0 = -1e30f, mr1 = -1e30f, lr0 = 0.f, lr1 = 0.f;

    const int brow = (lane & 7);
    const int bhi  = ((lane >> 4) & 1) * 8;
    const int bcolb = ((lane >> 3) & 1) * 16;

    for (int kt = 0; kt < 16; kt++) {
        if (kt + 1 < 16) {
            issue_kv(kt + 1);
            asm volatile("cp.async.wait_group 1;" ::: "memory");
        } else {
            asm volatile("cp.async.wait_group 0;" ::: "memory");
        }
        __syncthreads();
        const uint32_t ub = su + 32768 + (uint32_t)(kt & 1) * 65536;

        // ---- S = Q K^T (3-term split) ----
        float s[16][4] = {};
        #pragma unroll
        for (int np = 0; np < 8; np++) {
            #pragma unroll
            for (int ks = 0; ks < 4; ks++) {
                const int r = np * 16 + brow + bhi;
                uint32_t so = SMEM_SWIZZLE_128B((uint32_t)(r * 128 + ks * 32 + bcolb));
                uint32_t bh[4], bl[4];
                LDSM4(bh[0], bh[1], bh[2], bh[3], ub + so);
                LDSM4(bl[0], bl[1], bl[2], bl[3], ub + 16384 + so);
                MMA16816(s[2 * np],     qhf[ks], bh + 0);
                MMA16816(s[2 * np],     qhf[ks], bl + 0);
                MMA16816(s[2 * np],     qlf[ks], bh + 0);
                MMA16816(s[2 * np + 1], qhf[ks], bh + 2);
                MMA16816(s[2 * np + 1], qhf[ks], bl + 2);
                MMA16816(s[2 * np + 1], qlf[ks], bh + 2);
            }
        }

        // ---- online softmax ----
        float mx0 = -1e30f, mx1 = -1e30f;
        #pragma unroll
        for (int nt = 0; nt < 16; nt++) {
            s[nt][0] *= 0.125f; s[nt][1] *= 0.125f;
            s[nt][2] *= 0.125f; s[nt][3] *= 0.125f;
            mx0 = fmaxf(mx0, fmaxf(s[nt][0], s[nt][1]));
            mx1 = fmaxf(mx1, fmaxf(s[nt][2], s[nt][3]));
        }
        #pragma unroll
        for (int o = 1; o <= 2; o <<= 1) {
            mx0 = fmaxf(mx0, __shfl_xor_sync(0xffffffffu, mx0, o));
            mx1 = fmaxf(mx1, __shfl_xor_sync(0xffffffffu, mx1, o));
        }
        const float mn0 = fmaxf(mr0, mx0), mn1 = fmaxf(mr1, mx1);
        const float a0 = __expf(mr0 - mn0), a1 = __expf(mr1 - mn1);
        mr0 = mn0; mr1 = mn1;
        float ls0 = 0.f, ls1 = 0.f;
        #pragma unroll
        for (int nt = 0; nt < 16; nt++) {
            s[nt][0] = __expf(s[nt][0] - mn0);
            s[nt][1] = __expf(s[nt][1] - mn0);
            s[nt][2] = __expf(s[nt][2] - mn1);
            s[nt][3] = __expf(s[nt][3] - mn1);
            ls0 += s[nt][0] + s[nt][1];
            ls1 += s[nt][2] + s[nt][3];
        }
        #pragma unroll
        for (int o = 1; o <= 2; o <<= 1) {
            ls0 += __shfl_xor_sync(0xffffffffu, ls0, o);
            ls1 += __shfl_xor_sync(0xffffffffu, ls1, o);
        }
        lr0 = lr0 * a0 + ls0;
        lr1 = lr1 * a1 + ls1;
        #pragma unroll
        for (int nt2 = 0; nt2 < 8; nt2++) {
            accO[nt2][0] *= a0; accO[nt2][1] *= a0;
            accO[nt2][2] *= a1; accO[nt2][3] *= a1;
        }

        // ---- O += P V  (P hi/lo split; V hi+lo; 3-term) ----
        #pragma unroll
        for (int kp = 0; kp < 8; kp++) {
            uint32_t pfh[4], pfl[4];
            pk2split(s[2 * kp][0],     s[2 * kp][1],     pfh[0], pfl[0]);
            pk2split(s[2 * kp][2],     s[2 * kp][3],     pfh[1], pfl[1]);
            pk2split(s[2 * kp + 1][0], s[2 * kp + 1][1], pfh[2], pfl[2]);
            pk2split(s[2 * kp + 1][2], s[2 * kp + 1][3], pfh[3], pfl[3]);
            const uint32_t hoff = (uint32_t)(kp >> 2) * 8192;
            const int kb = (kp & 3) * 32;
            #pragma unroll
            for (int np = 0; np < 4; np++) {
                const int r = np * 16 + brow + bhi;
                uint32_t so = hoff + SMEM_SWIZZLE_128B((uint32_t)(r * 128 + kb + bcolb));
                uint32_t vh[4], vl[4];
                LDSM4(vh[0], vh[1], vh[2], vh[3], ub + 32768 + so);
                LDSM4(vl[0], vl[1], vl[2], vl[3], ub + 49152 + so);
                MMA16816(accO[2 * np],     pfh, vh + 0);
                MMA16816(accO[2 * np],     pfh, vl + 0);
                MMA16816(accO[2 * np],     pfl, vh + 0);
                MMA16816(accO[2 * np + 1], pfh, vh + 2);
                MMA16816(accO[2 * np + 1], pfh, vl + 2);
                MMA16816(accO[2 * np + 1], pfl, vh + 2);
            }
        }
        __syncthreads();
    }

    // ---- epilogue: O /= l, write bf16 hi/lo ----
    const float i0 = 1.0f / lr0, i1 = 1.0f / lr1;
    const int g = lane >> 2, tg = lane & 3;
    const size_t r0 = (size_t)b * SEQ + m0 + w * 16 + g;
    const size_t r1 = r0 + 8;
    #pragma unroll
    for (int nt2 = 0; nt2 < 8; nt2++) {
        const int d = nt2 * 8 + tg * 2;
        __nv_bfloat162 hp, lp;
        split2(accO[nt2][0] * i0, hp.x, lp.x);
        split2(accO[nt2][1] * i0, hp.y, lp.y);
        *(__nv_bfloat162*)(ah + r0 * DM + h * HD + d) = hp;
        *(__nv_bfloat162*)(al + r0 * DM + h * HD + d) = lp;
        split2(accO[nt2][2] * i1, hp.x, lp.x);
        split2(accO[nt2][3] * i1, hp.y, lp.y);
        *(__nv_bfloat162*)(ah + r1 * DM + h * HD + d) = hp;
        *(__nv_bfloat162*)(al + r1 * DM + h * HD + d) = lp;
    }
}

// ------------------------- host ---------------------------------------------
extern "C" void kernel_launch(void* const* d_in, const int* in_sizes, int n_in,
                              void* d_out, int out_size) {
    const float* x    = (const float*)d_in[0];
    const float* Wqkv = (const float*)d_in[1];
    const float* bqkv = (const float*)d_in[2];
    const float* Wo   = (const float*)d_in[3];
    const float* bo   = (const float*)d_in[4];
    float* out = (float*)d_out;

    __nv_bfloat16 *xh, *xl, *wqth, *wqtl, *woth, *wotl, *qkvh, *qkvl;
    __nv_bfloat16 *vth, *vtl, *ah, *al;
    cudaGetSymbolAddress((void**)&xh, g_xh);     cudaGetSymbolAddress((void**)&xl, g_xl);
    cudaGetSymbolAddress((void**)&wqth, g_wqth); cudaGetSymbolAddress((void**)&wqtl, g_wqtl);
    cudaGetSymbolAddress((void**)&woth, g_woth); cudaGetSymbolAddress((void**)&wotl, g_wotl);
    cudaGetSymbolAddress((void**)&qkvh, g_qkvh); cudaGetSymbolAddress((void**)&qkvl, g_qkvl);
    cudaGetSymbolAddress((void**)&vth, g_vth);   cudaGetSymbolAddress((void**)&vtl, g_vtl);
    cudaGetSymbolAddress((void**)&ah, g_ah);     cudaGetSymbolAddress((void**)&al, g_al);

    cudaFuncSetAttribute(k_gemm_qkv, cudaFuncAttributeMaxDynamicSharedMemorySize, SMEM_G128);
    cudaFuncSetAttribute(k_flash,    cudaFuncAttributeMaxDynamicSharedMemorySize, SMEM_FL);
    cudaFuncSetAttribute(k_proj,     cudaFuncAttributeMaxDynamicSharedMemorySize, SMEM_G128);

    k_split<<<(size_t)MTOT * DM / 1024, 256>>>(x, xh, xl);
    k_tsplit<<<dim3(QKVN / 32, DM / 32), dim3(32, 8)>>>(Wqkv, wqth, wqtl, DM, QKVN);
    k_tsplit<<<dim3(DM / 32, DM / 32), dim3(32, 8)>>>(Wo, woth, wotl, DM, DM);

    k_gemm_qkv<<<dim3(QKVN / 128, MTOT / 128), 256, SMEM_G128>>>(
        xh, xl, wqth, wqtl, bqkv, qkvh, qkvl);

    k_vt<<<dim3(SEQ / 32, HD / 32, BATCH * NKV), dim3(32, 8)>>>(qkvh, qkvl, vth, vtl);

    k_flash<<<dim3(SEQ / 128, NHEAD), 256, SMEM_FL>>>(qkvh, qkvl, vth, vtl, ah, al);

    k_proj<<<dim3(DM / 128, MTOT / 128), 256, SMEM_G128>>>(ah, al, woth, wotl, bo, out);
}

// round 6
// speedup vs baseline: 3.6245x; 1.0432x over previous
#include <cuda_runtime.h>
#include <cuda_bf16.h>
#include <cstdint>

#define SEQ   2048
#define DM    2048
#define NQ    32
#define NKV   8
#define HD    64
#define QKVN  3072
#define BATCH 2
#define MTOT  (BATCH * SEQ)   // 4096
#define NHEAD (BATCH * NQ)    // 64

// 0.125 * log2(e): folded into Q so flash softmax can use raw ex2
#define QSCALE 0.18033688011112042f

// ------------------------- scratch (device globals) -------------------------
__device__ __align__(128) __nv_bfloat16 g_xh[(size_t)MTOT * DM];
__device__ __align__(128) __nv_bfloat16 g_xl[(size_t)MTOT * DM];
__device__ __align__(128) __nv_bfloat16 g_wqth[(size_t)QKVN * DM];
__device__ __align__(128) __nv_bfloat16 g_wqtl[(size_t)QKVN * DM];
__device__ __align__(128) __nv_bfloat16 g_woth[(size_t)DM * DM];
__device__ __align__(128) __nv_bfloat16 g_wotl[(size_t)DM * DM];
__device__ __align__(128) __nv_bfloat16 g_qkvh[(size_t)MTOT * QKVN];
__device__ __align__(128) __nv_bfloat16 g_qkvl[(size_t)MTOT * QKVN];
__device__ __align__(128) __nv_bfloat16 g_vth[(size_t)BATCH * NKV * HD * SEQ];
__device__ __align__(128) __nv_bfloat16 g_vtl[(size_t)BATCH * NKV * HD * SEQ];
__device__ __align__(128) __nv_bfloat16 g_ah[(size_t)MTOT * DM];
__device__ __align__(128) __nv_bfloat16 g_al[(size_t)MTOT * DM];

// ------------------------- helpers ------------------------------------------
__device__ __forceinline__ uint32_t smem_u32(const void* p) {
    uint32_t a;
    asm("{ .reg .u64 t; cvta.to.shared.u64 t, %1; cvt.u32.u64 %0, t; }"
        : "=r"(a) : "l"(p));
    return a;
}

#define SMEM_SWIZZLE_128B(o) ((o) ^ (((o) >> 3) & 0x70))

__device__ __forceinline__ void cp16(uint32_t d, const void* s) {
    asm volatile("cp.async.cg.shared.global [%0], [%1], 16;" :: "r"(d), "l"(s));
}
#define CP_COMMIT() asm volatile("cp.async.commit_group;" ::: "memory")

#define LDSM4(R0, R1, R2, R3, A) \
    asm volatile("ldmatrix.sync.aligned.m8n8.x4.shared.b16 {%0,%1,%2,%3}, [%4];" \
                 : "=r"(R0), "=r"(R1), "=r"(R2), "=r"(R3) : "r"(A))
#define LDSM2(R0, R1, A) \
    asm volatile("ldmatrix.sync.aligned.m8n8.x2.shared.b16 {%0,%1}, [%2];" \
                 : "=r"(R0), "=r"(R1) : "r"(A))

#define MMA16816(C, A, B) \
    asm volatile("mma.sync.aligned.m16n8k16.row.col.f32.bf16.bf16.f32 " \
                 "{%0,%1,%2,%3}, {%4,%5,%6,%7}, {%8,%9}, {%0,%1,%2,%3};" \
                 : "+f"((C)[0]), "+f"((C)[1]), "+f"((C)[2]), "+f"((C)[3]) \
                 : "r"((A)[0]), "r"((A)[1]), "r"((A)[2]), "r"((A)[3]), \
                   "r"((B)[0]), "r"((B)[1]))

union B16x4 { uint2 v; __nv_bfloat16 b[4]; };

__device__ __forceinline__ void split2(float v, __nv_bfloat16& h, __nv_bfloat16& l) {
    h = __float2bfloat16(v);
    l = __float2bfloat16(v - __bfloat162float(h));
}
__device__ __forceinline__ void pk2split(float a, float b, uint32_t& hi, uint32_t& lo) {
    __nv_bfloat162 h, l;
    split2(a, h.x, l.x);
    split2(b, h.y, l.y);
    hi = *(uint32_t*)&h;
    lo = *(uint32_t*)&l;
}
__device__ __forceinline__ float ex2(float x) {
    float y;
    asm("ex2.approx.ftz.f32 %0, %1;" : "=f"(y) : "f"(x));
    return y;
}

// ------------------------- mma.sync GEMM core -------------------------------
// BM=128 fixed, 8 warps (2 x 4); warp tile 64 x (BN/4); NT = BN/32 n8-tiles.
template <int BN>
__device__ __forceinline__ void gemm_mma(
    char* smem, int tid,
    const __nv_bfloat16* __restrict__ Ah, const __nv_bfloat16* __restrict__ Al, int lda,
    const __nv_bfloat16* __restrict__ Bh, const __nv_bfloat16* __restrict__ Bl, int ldb,
    int K, float acc[4][BN / 32][4])
{
    constexpr int NT    = BN / 32;
    constexpr int ABY   = 128 * 128;
    constexpr int BBY   = BN * 128;
    constexpr int STAGE = 2 * ABY + 2 * BBY;

    const uint32_t su = smem_u32(smem);
    const int lane = tid & 31, warp = tid >> 5;
    const int wm = warp & 1, wn = warp >> 1;
    const int arow  = wm * 64 + (lane & 15);
    const int acolb = (lane >> 4) * 16;
    const int brow  = wn * (BN / 4) + (lane & 7);
    const int bcolb = ((lane >> 3) & 1) * 16;
    const int nch = K >> 6;

    auto issue = [&](int c) {
        const int k0 = c << 6;
        const uint32_t ub = su + (uint32_t)(c & 1) * STAGE;
        #pragma unroll
        for (int t = 0; t < 4; t++) {
            int i = tid + t * 256;
            int r = i >> 3, q = i & 7;
            uint32_t so = SMEM_SWIZZLE_128B((uint32_t)(r * 128 + q * 16));
            size_t off = (size_t)r * lda + k0 + q * 8;
            cp16(ub + so, Ah + off);
            cp16(ub + ABY + so, Al + off);
        }
        #pragma unroll
        for (int t = 0; t < (BN * 8) / 256; t++) {
            int i = tid + t * 256;
            int r = i >> 3, q = i & 7;
            uint32_t so = SMEM_SWIZZLE_128B((uint32_t)(r * 128 + q * 16));
            size_t off = (size_t)r * ldb + k0 + q * 8;
            cp16(ub + 2 * ABY + so, Bh + off);
            cp16(ub + 2 * ABY + BBY + so, Bl + off);
        }
        CP_COMMIT();
    };

    issue(0);
    for (int c = 0; c < nch; c++) {
        if (c + 1 < nch) {
            issue(c + 1);
            asm volatile("cp.async.wait_group 1;" ::: "memory");
        } else {
            asm volatile("cp.async.wait_group 0;" ::: "memory");
        }
        __syncthreads();
        const uint32_t ub = su + (uint32_t)(c & 1) * STAGE;
        #pragma unroll
        for (int ks = 0; ks < 4; ks++) {
            const int kb = ks * 32;
            uint32_t ahr[4][4], alr[4][4], bhr[NT][2], blr[NT][2];
            #pragma unroll
            for (int mt = 0; mt < 4; mt++) {
                uint32_t so = SMEM_SWIZZLE_128B(
                    (uint32_t)((arow + mt * 16) * 128 + kb + acolb));
                LDSM4(ahr[mt][0], ahr[mt][1], ahr[mt][2], ahr[mt][3], ub + so);
                LDSM4(alr[mt][0], alr[mt][1], alr[mt][2], alr[mt][3], ub + ABY + so);
            }
            #pragma unroll
            for (int nt = 0; nt < NT; nt++) {
                uint32_t so = SMEM_SWIZZLE_128B(
                    (uint32_t)((brow + nt * 8) * 128 + kb + bcolb));
                LDSM2(bhr[nt][0], bhr[nt][1], ub + 2 * ABY + so);
                LDSM2(blr[nt][0], blr[nt][1], ub + 2 * ABY + BBY + so);
            }
            #pragma unroll
            for (int mt = 0; mt < 4; mt++)
                #pragma unroll
                for (int nt = 0; nt < NT; nt++) {
                    MMA16816(acc[mt][nt], ahr[mt], bhr[nt]);
                    MMA16816(acc[mt][nt], ahr[mt], blr[nt]);
                    MMA16816(acc[mt][nt], alr[mt], bhr[nt]);
                }
        }
        __syncthreads();
    }
}

static constexpr int SMEM_QKV  = 2 * (2 * 128 * 128 + 2 * 96 * 128);   // 114688
static constexpr int SMEM_PROJ = 2 * (2 * 128 * 128 + 2 * 64 * 128);   //  98304
static constexpr int SMEM_FL   = 32768 + 2 * 65536;                    // 163840

// ------------------------- prep kernels -------------------------------------
__global__ __launch_bounds__(256) void k_split(const float* __restrict__ x,
                                               __nv_bfloat16* __restrict__ xh,
                                               __nv_bfloat16* __restrict__ xl) {
    size_t i = ((size_t)blockIdx.x * 256 + threadIdx.x) * 4;
    float4 v = *(const float4*)(x + i);
    B16x4 h, l;
    split2(v.x, h.b[0], l.b[0]); split2(v.y, h.b[1], l.b[1]);
    split2(v.z, h.b[2], l.b[2]); split2(v.w, h.b[3], l.b[3]);
    *(uint2*)(xh + i) = h.v;
    *(uint2*)(xl + i) = l.v;
}

__global__ __launch_bounds__(256) void k_tsplit(const float* __restrict__ W,
                                                __nv_bfloat16* __restrict__ Th,
                                                __nv_bfloat16* __restrict__ Tl,
                                                int K, int N) {
    __shared__ float t[32][33];
    const int n0 = blockIdx.x * 32, k0 = blockIdx.y * 32;
    const int tx = threadIdx.x, ty = threadIdx.y;
    #pragma unroll
    for (int i = 0; i < 4; i++)
        t[ty * 4 + i][tx] = W[(size_t)(k0 + ty * 4 + i) * N + n0 + tx];
    __syncthreads();
    #pragma unroll
    for (int i = 0; i < 4; i++) {
        float v = t[tx][ty * 4 + i];
        __nv_bfloat16 h, l; split2(v, h, l);
        size_t o = (size_t)(n0 + ty * 4 + i) * K + k0 + tx;
        Th[o] = h; Tl[o] = l;
    }
}

__global__ __launch_bounds__(256) void k_vt(const __nv_bfloat16* __restrict__ qh,
                                            const __nv_bfloat16* __restrict__ ql,
                                            __nv_bfloat16* __restrict__ vth,
                                            __nv_bfloat16* __restrict__ vtl) {
    __shared__ __nv_bfloat16 th[32][33], tl[32][33];
    const int bk = blockIdx.z, b = bk >> 3, kv = bk & 7;
    const int s0 = blockIdx.x * 32, n0 = blockIdx.y * 32;
    const int tx = threadIdx.x, ty = threadIdx.y;
    #pragma unroll
    for (int i = 0; i < 4; i++) {
        size_t src = ((size_t)b * SEQ + s0 + ty * 4 + i) * QKVN + (NQ + NKV) * HD + kv * HD + n0 + tx;
        th[ty * 4 + i][tx] = qh[src];
        tl[ty * 4 + i][tx] = ql[src];
    }
    __syncthreads();
    #pragma unroll
    for (int i = 0; i < 4; i++) {
        size_t dst = ((size_t)bk * HD + n0 + ty * 4 + i) * SEQ + s0 + tx;
        vth[dst] = th[tx][ty * 4 + i];
        vtl[dst] = tl[tx][ty * 4 + i];
    }
}

// ------------------------- GEMM kernels (qkv, proj) -------------------------
// BN = 96 -> grid (3072/96=32, 4096/128=32) = 1024 blocks (good wave fit).
__global__ __launch_bounds__(256, 1) void k_gemm_qkv(
    const __nv_bfloat16* __restrict__ xh, const __nv_bfloat16* __restrict__ xl,
    const __nv_bfloat16* __restrict__ wth, const __nv_bfloat16* __restrict__ wtl,
    const float* __restrict__ bias,
    __nv_bfloat16* __restrict__ qh, __nv_bfloat16* __restrict__ ql) {
    extern __shared__ char smem[];
    const int tid = threadIdx.x;
    const size_t m0 = (size_t)blockIdx.y * 128, n0 = (size_t)blockIdx.x * 96;
    float acc[4][3][4] = {};
    gemm_mma<96>(smem, tid, xh + m0 * DM, xl + m0 * DM, DM,
                 wth + n0 * DM, wtl + n0 * DM, DM, DM, acc);
    const int lane = tid & 31, warp = tid >> 5;
    const int wm = warp & 1, wn = warp >> 1;
    const int g = lane >> 2, tg = lane & 3;
    #pragma unroll
    for (int mt = 0; mt < 4; mt++)
        #pragma unroll
        for (int half = 0; half < 2; half++) {
            const size_t m = m0 + wm * 64 + mt * 16 + g + half * 8;
            #pragma unroll
            for (int nt = 0; nt < 3; nt++) {
                const int nl = wn * 24 + nt * 8 + tg * 2;
                const int col = (int)n0 + nl;
                // fold softmax scale (0.125*log2e) into the Q region
                const float sc0 = (col     < NQ * HD) ? QSCALE : 1.0f;
                const float sc1 = (col + 1 < NQ * HD) ? QSCALE : 1.0f;
                float v0 = (acc[mt][nt][half * 2 + 0] + bias[col])     * sc0;
                float v1 = (acc[mt][nt][half * 2 + 1] + bias[col + 1]) * sc1;
                __nv_bfloat162 hp, lp;
                split2(v0, hp.x, lp.x);
                split2(v1, hp.y, lp.y);
                *(__nv_bfloat162*)(qh + m * QKVN + col) = hp;
                *(__nv_bfloat162*)(ql + m * QKVN + col) = lp;
            }
        }
}

// BN = 64 -> grid (2048/64=32, 32) = 1024 blocks.
__global__ __launch_bounds__(256, 1) void k_proj(
    const __nv_bfloat16* __restrict__ ah, const __nv_bfloat16* __restrict__ al,
    const __nv_bfloat16* __restrict__ wth, const __nv_bfloat16* __restrict__ wtl,
    const float* __restrict__ bias, float* __restrict__ out) {
    extern __shared__ char smem[];
    const int tid = threadIdx.x;
    const size_t m0 = (size_t)blockIdx.y * 128, n0 = (size_t)blockIdx.x * 64;
    float acc[4][2][4] = {};
    gemm_mma<64>(smem, tid, ah + m0 * DM, al + m0 * DM, DM,
                 wth + n0 * DM, wtl + n0 * DM, DM, DM, acc);
    const int lane = tid & 31, warp = tid >> 5;
    const int wm = warp & 1, wn = warp >> 1;
    const int g = lane >> 2, tg = lane & 3;
    #pragma unroll
    for (int mt = 0; mt < 4; mt++)
        #pragma unroll
        for (int half = 0; half < 2; half++) {
            const size_t m = m0 + wm * 64 + mt * 16 + g + half * 8;
            float* dst = out + m * DM + n0;
            #pragma unroll
            for (int nt = 0; nt < 2; nt++) {
                const int nl = wn * 16 + nt * 8 + tg * 2;
                float2 v;
                v.x = acc[mt][nt][half * 2 + 0] + bias[n0 + nl];
                v.y = acc[mt][nt][half * 2 + 1] + bias[n0 + nl + 1];
                *(float2*)(dst + nl) = v;
            }
        }
}

// ------------------------- fused flash attention ----------------------------
// Grid (SEQ/128, NHEAD). 8 warps, warp w owns Q rows [w*16, w*16+16).
// Q pre-scaled by 0.125*log2e -> softmax in base-2 (bare ex2).
__global__ __launch_bounds__(256, 1) void k_flash(
    const __nv_bfloat16* __restrict__ qkvh, const __nv_bfloat16* __restrict__ qkvl,
    const __nv_bfloat16* __restrict__ vth, const __nv_bfloat16* __restrict__ vtl,
    __nv_bfloat16* __restrict__ ah, __nv_bfloat16* __restrict__ al)
{
    extern __shared__ char smem[];
    const uint32_t su = smem_u32(smem);
    const int tid = threadIdx.x, lane = tid & 31, w = tid >> 5;
    const int z = blockIdx.y, b = z >> 5, h = z & 31, kvh = h >> 2;
    const int m0 = blockIdx.x * 128;

    const __nv_bfloat16* Qh = qkvh + ((size_t)(b * SEQ + m0)) * QKVN + h * HD;
    const __nv_bfloat16* Ql = qkvl + ((size_t)(b * SEQ + m0)) * QKVN + h * HD;
    const __nv_bfloat16* Kh = qkvh + (size_t)b * SEQ * QKVN + NQ * HD + kvh * HD;
    const __nv_bfloat16* Kl = qkvl + (size_t)b * SEQ * QKVN + NQ * HD + kvh * HD;
    const __nv_bfloat16* Vh = vth + (size_t)(b * NKV + kvh) * HD * SEQ;
    const __nv_bfloat16* Vl = vtl + (size_t)(b * NKV + kvh) * HD * SEQ;

    #pragma unroll
    for (int t = 0; t < 4; t++) {
        int i = tid + t * 256;
        int r = i >> 3, q = i & 7;
        uint32_t so = SMEM_SWIZZLE_128B((uint32_t)(r * 128 + q * 16));
        size_t off = (size_t)r * QKVN + q * 8;
        cp16(su + so, Qh + off);
        cp16(su + 16384 + so, Ql + off);
    }
    CP_COMMIT();

    auto issue_kv = [&](int kt) {
        uint32_t ub = su + 32768 + (uint32_t)(kt & 1) * 65536;
        #pragma unroll
        for (int t = 0; t < 4; t++) {
            int i = tid + t * 256;
            int r = i >> 3, q = i & 7;
            uint32_t so = SMEM_SWIZZLE_128B((uint32_t)(r * 128 + q * 16));
            size_t off = (size_t)(kt * 128 + r) * QKVN + q * 8;
            cp16(ub + so, Kh + off);
            cp16(ub + 16384 + so, Kl + off);
        }
        #pragma unroll
        for (int t = 0; t < 4; t++) {
            int i = tid + t * 256;
            int d = i >> 4, q = i & 15;
            uint32_t so = (uint32_t)(q >> 3) * 8192 +
                          SMEM_SWIZZLE_128B((uint32_t)(d * 128 + (q & 7) * 16));
            size_t off = (size_t)d * SEQ + kt * 128 + q * 8;
            cp16(ub + 32768 + so, Vh + off);
            cp16(ub + 49152 + so, Vl + off);
        }
        CP_COMMIT();
    };

    issue_kv(0);
    asm volatile("cp.async.wait_group 1;" ::: "memory");
    __syncthreads();

    uint32_t qhf[4][4], qlf[4][4];
    {
        const int arow = w * 16 + (lane & 15);
        const int acolb = (lane >> 4) * 16;
        #pragma unroll
        for (int ks = 0; ks < 4; ks++) {
            uint32_t so = SMEM_SWIZZLE_128B((uint32_t)(arow * 128 + ks * 32 + acolb));
            LDSM4(qhf[ks][0], qhf[ks][1], qhf[ks][2], qhf[ks][3], su + so);
            LDSM4(qlf[ks][0], qlf[ks][1], qlf[ks][2], qlf[ks][3], su + 16384 + so);
        }
    }

    float accO[8][4] = {};
    float mr0 = -1e30f, mr1 = -1e30f, lr0 = 0.f, lr1 = 0.f;

    const int brow = (lane & 7);
    const int bhi  = ((lane >> 4) & 1) * 8;
    const int bcolb = ((lane >> 3) & 1) * 16;

    for (int kt = 0; kt < 16; kt++) {
        if (kt + 1 < 16) {
            issue_kv(kt + 1);
            asm volatile("cp.async.wait_group 1;" ::: "memory");
        } else {
            asm volatile("cp.async.wait_group 0;" ::: "memory");
        }
        __syncthreads();
        const uint32_t ub = su + 32768 + (uint32_t)(kt & 1) * 65536;

        // ---- S = Q K^T (3-term split); Q pre-scaled ----
        float s[16][4] = {};
        #pragma unroll
        for (int np = 0; np < 8; np++) {
            #pragma unroll
            for (int ks = 0; ks < 4; ks++) {
                const int r = np * 16 + brow + bhi;
                uint32_t so = SMEM_SWIZZLE_128B((uint32_t)(r * 128 + ks * 32 + bcolb));
                uint32_t bh[4], bl[4];
                LDSM4(bh[0], bh[1], bh[2], bh[3], ub + so);
                LDSM4(bl[0], bl[1], bl[2], bl[3], ub + 16384 + so);
                MMA16816(s[2 * np],     qhf[ks], bh + 0);
                MMA16816(s[2 * np],     qhf[ks], bl + 0);
                MMA16816(s[2 * np],     qlf[ks], bh + 0);
                MMA16816(s[2 * np + 1], qhf[ks], bh + 2);
                MMA16816(s[2 * np + 1], qhf[ks], bl + 2);
                MMA16816(s[2 * np + 1], qlf[ks], bh + 2);
            }
        }

        // ---- online softmax (base 2) ----
        float mx0 = -1e30f, mx1 = -1e30f;
        #pragma unroll
        for (int nt = 0; nt < 16; nt++) {
            mx0 = fmaxf(mx0, fmaxf(s[nt][0], s[nt][1]));
            mx1 = fmaxf(mx1, fmaxf(s[nt][2], s[nt][3]));
        }
        #pragma unroll
        for (int o = 1; o <= 2; o <<= 1) {
            mx0 = fmaxf(mx0, __shfl_xor_sync(0xffffffffu, mx0, o));
            mx1 = fmaxf(mx1, __shfl_xor_sync(0xffffffffu, mx1, o));
        }
        const float mn0 = fmaxf(mr0, mx0), mn1 = fmaxf(mr1, mx1);
        const float a0 = ex2(mr0 - mn0), a1 = ex2(mr1 - mn1);
        mr0 = mn0; mr1 = mn1;
        float ls0 = 0.f, ls1 = 0.f;
        #pragma unroll
        for (int nt = 0; nt < 16; nt++) {
            s[nt][0] = ex2(s[nt][0] - mn0);
            s[nt][1] = ex2(s[nt][1] - mn0);
            s[nt][2] = ex2(s[nt][2] - mn1);
            s[nt][3] = ex2(s[nt][3] - mn1);
            ls0 += s[nt][0] + s[nt][1];
            ls1 += s[nt][2] + s[nt][3];
        }
        #pragma unroll
        for (int o = 1; o <= 2; o <<= 1) {
            ls0 += __shfl_xor_sync(0xffffffffu, ls0, o);
            ls1 += __shfl_xor_sync(0xffffffffu, ls1, o);
        }
        lr0 = lr0 * a0 + ls0;
        lr1 = lr1 * a1 + ls1;
        #pragma unroll
        for (int nt2 = 0; nt2 < 8; nt2++) {
            accO[nt2][0] *= a0; accO[nt2][1] *= a0;
            accO[nt2][2] *= a1; accO[nt2][3] *= a1;
        }

        // ---- O += P V (P hi/lo; V hi+lo; 3-term) ----
        #pragma unroll
        for (int kp = 0; kp < 8; kp++) {
            uint32_t pfh[4], pfl[4];
            pk2split(s[2 * kp][0],     s[2 * kp][1],     pfh[0], pfl[0]);
            pk2split(s[2 * kp][2],     s[2 * kp][3],     pfh[1], pfl[1]);
            pk2split(s[2 * kp + 1][0], s[2 * kp + 1][1], pfh[2], pfl[2]);
            pk2split(s[2 * kp + 1][2], s[2 * kp + 1][3], pfh[3], pfl[3]);
            const uint32_t hoff = (uint32_t)(kp >> 2) * 8192;
            const int kb = (kp & 3) * 32;
            #pragma unroll
            for (int np = 0; np < 4; np++) {
                const int r = np * 16 + brow + bhi;
                uint32_t so = hoff + SMEM_SWIZZLE_128B((uint32_t)(r * 128 + kb + bcolb));
                uint32_t vh[4], vl[4];
                LDSM4(vh[0], vh[1], vh[2], vh[3], ub + 32768 + so);
                LDSM4(vl[0], vl[1], vl[2], vl[3], ub + 49152 + so);
                MMA16816(accO[2 * np],     pfh, vh + 0);
                MMA16816(accO[2 * np],     pfh, vl + 0);
                MMA16816(accO[2 * np],     pfl, vh + 0);
                MMA16816(accO[2 * np + 1], pfh, vh + 2);
                MMA16816(accO[2 * np + 1], pfh, vl + 2);
                MMA16816(accO[2 * np + 1], pfl, vh + 2);
            }
        }
        __syncthreads();
    }

    const float i0 = 1.0f / lr0, i1 = 1.0f / lr1;
    const int g = lane >> 2, tg = lane & 3;
    const size_t r0 = (size_t)b * SEQ + m0 + w * 16 + g;
    const size_t r1 = r0 + 8;
    #pragma unroll
    for (int nt2 = 0; nt2 < 8; nt2++) {
        const int d = nt2 * 8 + tg * 2;
        __nv_bfloat162 hp, lp;
        split2(accO[nt2][0] * i0, hp.x, lp.x);
        split2(accO[nt2][1] * i0, hp.y, lp.y);
        *(__nv_bfloat162*)(ah + r0 * DM + h * HD + d) = hp;
        *(__nv_bfloat162*)(al + r0 * DM + h * HD + d) = lp;
        split2(accO[nt2][2] * i1, hp.x, lp.x);
        split2(accO[nt2][3] * i1, hp.y, lp.y);
        *(__nv_bfloat162*)(ah + r1 * DM + h * HD + d) = hp;
        *(__nv_bfloat162*)(al + r1 * DM + h * HD + d) = lp;
    }
}

// ------------------------- host ---------------------------------------------
extern "C" void kernel_launch(void* const* d_in, const int* in_sizes, int n_in,
                              void* d_out, int out_size) {
    const float* x    = (const float*)d_in[0];
    const float* Wqkv = (const float*)d_in[1];
    const float* bqkv = (const float*)d_in[2];
    const float* Wo   = (const float*)d_in[3];
    const float* bo   = (const float*)d_in[4];
    float* out = (float*)d_out;

    __nv_bfloat16 *xh, *xl, *wqth, *wqtl, *woth, *wotl, *qkvh, *qkvl;
    __nv_bfloat16 *vth, *vtl, *ah, *al;
    cudaGetSymbolAddress((void**)&xh, g_xh);     cudaGetSymbolAddress((void**)&xl, g_xl);
    cudaGetSymbolAddress((void**)&wqth, g_wqth); cudaGetSymbolAddress((void**)&wqtl, g_wqtl);
    cudaGetSymbolAddress((void**)&woth, g_woth); cudaGetSymbolAddress((void**)&wotl, g_wotl);
    cudaGetSymbolAddress((void**)&qkvh, g_qkvh); cudaGetSymbolAddress((void**)&qkvl, g_qkvl);
    cudaGetSymbolAddress((void**)&vth, g_vth);   cudaGetSymbolAddress((void**)&vtl, g_vtl);
    cudaGetSymbolAddress((void**)&ah, g_ah);     cudaGetSymbolAddress((void**)&al, g_al);

    cudaFuncSetAttribute(k_gemm_qkv, cudaFuncAttributeMaxDynamicSharedMemorySize, SMEM_QKV);
    cudaFuncSetAttribute(k_flash,    cudaFuncAttributeMaxDynamicSharedMemorySize, SMEM_FL);
    cudaFuncSetAttribute(k_proj,     cudaFuncAttributeMaxDynamicSharedMemorySize, SMEM_PROJ);

    k_split<<<(size_t)MTOT * DM / 1024, 256>>>(x, xh, xl);
    k_tsplit<<<dim3(QKVN / 32, DM / 32), dim3(32, 8)>>>(Wqkv, wqth, wqtl, DM, QKVN);
    k_tsplit<<<dim3(DM / 32, DM / 32), dim3(32, 8)>>>(Wo, woth, wotl, DM, DM);

    k_gemm_qkv<<<dim3(QKVN / 96, MTOT / 128), 256, SMEM_QKV>>>(
        xh, xl, wqth, wqtl, bqkv, qkvh, qkvl);

    k_vt<<<dim3(SEQ / 32, HD / 32, BATCH * NKV), dim3(32, 8)>>>(qkvh, qkvl, vth, vtl);

    k_flash<<<dim3(SEQ / 128, NHEAD), 256, SMEM_FL>>>(qkvh, qkvl, vth, vtl, ah, al);

    k_proj<<<dim3(DM / 64, MTOT / 128), 256, SMEM_PROJ>>>(ah, al, woth, wotl, bo, out);
}